// round 10
// baseline (speedup 1.0000x reference)
#include <cuda_runtime.h>
#include <math.h>

#define NB 1024
#define NS 512
#define NM (NB*NS)
#define G3 384
#define RB 7

typedef unsigned long long u64;

__device__ float g_xenc[NB*128];
__device__ float g_h0[NB*128];
__device__ float g_gxx[NB*G3];
__device__ float g_yxc[NB*128];
__device__ float g_agt[100*G3];
__device__ float g_tgt[4*G3];
__device__ float g_ayt[100*128];
__device__ float g_tyt[4*128];
__device__ float g_ct[400*G3];

__device__ __forceinline__ void fma2(u64& d, u64 a, u64 b) {
    asm("fma.rn.f32x2 %0, %1, %2, %0;" : "+l"(d) : "l"(a), "l"(b));
}
__device__ __forceinline__ u64 dup2(float v) {
    u64 r; asm("mov.b64 %0, {%1, %1};" : "=l"(r) : "f"(v)); return r;
}
__device__ __forceinline__ float2 lohi(u64 v) {
    float2 r; asm("mov.b64 {%0, %1}, %2;" : "=f"(r.x), "=f"(r.y) : "l"(v)); return r;
}
__device__ __forceinline__ float rcpa(float x) {
    float r; asm("rcp.approx.f32 %0, %1;" : "=f"(r) : "f"(x)); return r;
}
__device__ __forceinline__ float sigf(float x) {
    return rcpa(1.f + __expf(-x));
}
__device__ __forceinline__ float tanhc(float v) {
    v = fminf(fmaxf(v, -20.f), 20.f);
    float e = __expf(-2.f*v);
    return (1.f - e) * rcpa(1.f + e);
}
__device__ __forceinline__ void cpa16(unsigned dst, const void* src) {
    asm volatile("cp.async.cg.shared.global [%0], [%1], 16;" :: "r"(dst), "l"(src));
}

// ---------------- Phase A ----------------
#define GBM 64
#define GBN 64
#define GBK 32
__device__ __forceinline__ void gemm_body(
    const float* __restrict__ in,
    const float* __restrict__ W, int ldw, int wofs,
    const float* __restrict__ bias,
    float* __restrict__ out, int ldout, int act,
    int m0, int n0, int tid)
{
    __shared__ float As[GBK][GBM+4];
    __shared__ float Bs[GBK][GBN+4];
    int tx = tid & 15, ty = tid >> 4;
    float acc[4][4] = {};
    for (int k0 = 0; k0 < 128; k0 += GBK) {
        for (int l = tid; l < GBM*GBK/4; l += 256) {
            int row = l >> 3, c4 = l & 7;
            float4 v = *(const float4*)&in[(size_t)(m0+row)*128 + k0 + c4*4];
            As[c4*4+0][row] = v.x; As[c4*4+1][row] = v.y;
            As[c4*4+2][row] = v.z; As[c4*4+3][row] = v.w;
        }
        for (int l = tid; l < GBN*GBK; l += 256) {
            int row = l >> 5, kk = l & 31;
            Bs[kk][row] = W[(size_t)(n0+row)*ldw + wofs + k0 + kk];
        }
        __syncthreads();
        #pragma unroll
        for (int k = 0; k < GBK; k++) {
            float4 a4 = *(const float4*)&As[k][ty*4];
            float4 b4 = *(const float4*)&Bs[k][tx*4];
            float af[4] = {a4.x,a4.y,a4.z,a4.w};
            float bf[4] = {b4.x,b4.y,b4.z,b4.w};
            #pragma unroll
            for (int i = 0; i < 4; i++)
                #pragma unroll
                for (int j = 0; j < 4; j++)
                    acc[i][j] = fmaf(af[i], bf[j], acc[i][j]);
        }
        __syncthreads();
    }
    #pragma unroll
    for (int i = 0; i < 4; i++) {
        int m = m0 + ty*4 + i;
        #pragma unroll
        for (int j = 0; j < 4; j++) {
            int n = n0 + tx*4 + j;
            float v = acc[i][j] + bias[n];
            if (act) v = tanhf(v);
            out[(size_t)m*ldout + n] = v;
        }
    }
}

__global__ void __launch_bounds__(256) k_gemm(
    const float* __restrict__ in,
    const float* __restrict__ W, int ldw,
    const float* __restrict__ bias,
    float* __restrict__ out, int act)
{
    gemm_body(in, W, ldw, 0, bias, out, 128, act,
              blockIdx.y*GBM, blockIdx.x*GBN, threadIdx.x);
}

// z=0..2: gemms off g_xenc; z=3: build combined gate table g_ct
__global__ void __launch_bounds__(256) k_gemm3(
    const float* __restrict__ W_ih, const float* __restrict__ b_ih,
    const float* __restrict__ yW1, const float* __restrict__ yb1,
    const float* __restrict__ h0W, const float* __restrict__ h0b)
{
    int z = blockIdx.z;
    if (z == 3) {
        int lin = blockIdx.y*6 + blockIdx.x;   // 0..95
        #pragma unroll
        for (int q = 0; q < 5; q++) {
            int p = lin*5 + q;
            if (p < 400) {
                int av = p >> 2, tv = p & 3;
                for (int j = threadIdx.x; j < G3; j += 256)
                    g_ct[p*G3 + j] = g_agt[av*G3 + j] + g_tgt[tv*G3 + j];
            }
        }
        return;
    }
    const float *W, *bias; float* out; int ldw, wofs, Nout, ldout, act;
    if (z == 0)      { W=W_ih; bias=b_ih; out=g_gxx; ldw=177; wofs=0;   Nout=384; ldout=384; act=0; }
    else if (z == 1) { W=yW1;  bias=yb1;  out=g_yxc; ldw=304; wofs=128; Nout=128; ldout=128; act=0; }
    else             { W=h0W;  bias=h0b;  out=g_h0;  ldw=128; wofs=0;   Nout=128; ldout=128; act=1; }
    if ((int)blockIdx.x*GBN >= Nout) return;
    gemm_body(g_xenc, W, ldw, wofs, bias, out, ldout, act,
              blockIdx.y*GBM, blockIdx.x*GBN, threadIdx.x);
}

__global__ void __launch_bounds__(384) k_tab(
    const float* __restrict__ a_emb, const float* __restrict__ t_emb,
    const float* __restrict__ W_ih, const float* __restrict__ yW1)
{
    __shared__ float e[32];
    int bid = blockIdx.x, j = threadIdx.x;
    if (bid < 100) {
        int m = bid;
        if (j < 32) e[j] = a_emb[m*32+j];
        __syncthreads();
        float s = 0.f;
        #pragma unroll
        for (int k = 0; k < 32; k++) s += e[k]*W_ih[(size_t)j*177 + 128 + k];
        g_agt[m*G3 + j] = s;
    } else if (bid < 104) {
        int m = bid - 100;
        if (j < 16) e[j] = t_emb[m*16+j];
        __syncthreads();
        float s = 0.f;
        #pragma unroll
        for (int k = 0; k < 16; k++) s += e[k]*W_ih[(size_t)j*177 + 160 + k];
        g_tgt[m*G3 + j] = s;
    } else if (bid < 204) {
        int m = bid - 104;
        if (j < 32) e[j] = a_emb[m*32+j];
        __syncthreads();
        if (j < 128) {
            float s = 0.f;
            #pragma unroll
            for (int k = 0; k < 32; k++) s += e[k]*yW1[(size_t)j*304 + 256 + k];
            g_ayt[m*128 + j] = s;
        }
    } else {
        int m = bid - 204;
        if (j < 16) e[j] = t_emb[m*16+j];
        __syncthreads();
        if (j < 128) {
            float s = 0.f;
            #pragma unroll
            for (int k = 0; k < 16; k++) s += e[k]*yW1[(size_t)j*304 + 288 + k];
            g_tyt[m*128 + j] = s;
        }
    }
}

// ---------------- Phase B: gate-split recurrence (2 warps/SMSP) ----------------
// 256 threads: grp 0 (warps 0-3) owns gates r,n (computes nn locally);
// grp 1 (warps 4-7) owns gate z + the h update. SMSP k pairs A-warp k with B-warp k.
__global__ void __launch_bounds__(256,1) k_rec(
    const int* __restrict__ a, const int* __restrict__ t,
    const float* __restrict__ y, const float* __restrict__ mask,
    const float* __restrict__ W_hh, const float* __restrict__ b_hh,
    const float* __restrict__ W_ih,
    float* __restrict__ dout)
{
    extern __shared__ float sm[];
    float* Wsh = sm;                   // 384*132
    float* hb  = Wsh + 384*132;        // 2 * RB*128
    float* nsh = hb + 2*RB*128;        // RB*128

    int tid = threadIdx.x;
    int jp  = tid & 127;
    int grp = tid >> 7;
    int b0  = blockIdx.x * RB;

    for (int idx = tid; idx < 384*128; idx += 256)
        Wsh[(idx>>7)*132 + (idx&127)] = W_hh[idx];

    int bidx[RB];
    #pragma unroll
    for (int r = 0; r < RB; r++) {
        int b = b0 + r; if (b > NB-1) b = NB-1;
        bidx[r] = b;
    }

    float* hseq = dout + (size_t)NM*5;

    if (grp == 0) {
        // ---- group A: gates r (0) and n (2) ----
        float wy0 = W_ih[jp*177 + 176];
        float wy2 = W_ih[(jp+256)*177 + 176];
        float bh0 = b_hh[jp], bh2 = b_hh[jp+256];
        float base0[RB], gxx2[RB];
        #pragma unroll
        for (int r = 0; r < RB; r++) {
            base0[r] = bh0 + g_gxx[(size_t)bidx[r]*G3 + jp];
            gxx2[r]  = g_gxx[(size_t)bidx[r]*G3 + jp + 256];
        }
        const ulonglong2* W0 = (const ulonglong2*)(Wsh + (size_t)jp*132);
        const ulonglong2* W2 = (const ulonglong2*)(Wsh + (size_t)(jp+256)*132);

        float yv[RB], g0[RB], g2[RB];
        #pragma unroll
        for (int r = 0; r < RB; r++) {
            int base = bidx[r]*NS;
            int av = a[base], tv = t[base];
            yv[r] = y[base];
            int ct = (av*4 + tv)*G3 + jp;
            g0[r] = g_ct[ct];
            g2[r] = g_ct[ct + 256];
        }
        __syncthreads();   // W + h0 (written by B) ready

        int rd = 0;
        for (int s = 0; s < NS; s++) {
            int avn[RB], tvn[RB]; float yn[RB];
            int sn = (s+1 < NS) ? s+1 : s;
            #pragma unroll
            for (int r = 0; r < RB; r++) {
                int bn = bidx[r]*NS + sn;
                avn[r] = a[bn]; tvn[r] = t[bn]; yn[r] = y[bn];
            }

            u64 a0[RB], a2[RB];
            #pragma unroll
            for (int r = 0; r < RB; r++) { a0[r] = 0ull; a2[r] = 0ull; }
            const ulonglong2* hp = (const ulonglong2*)(hb + rd*(RB*128));
            #pragma unroll 4
            for (int k4 = 0; k4 < 32; k4++) {
                ulonglong2 w0 = W0[k4], w2 = W2[k4];
                #pragma unroll
                for (int r = 0; r < RB; r++) {
                    ulonglong2 hv = hp[r*32 + k4];
                    fma2(a0[r], w0.x, hv.x); fma2(a0[r], w0.y, hv.y);
                    fma2(a2[r], w2.x, hv.x); fma2(a2[r], w2.y, hv.y);
                }
            }

            float g0n[RB], g2n[RB];
            #pragma unroll
            for (int r = 0; r < RB; r++) {
                int ct = (avn[r]*4 + tvn[r])*G3 + jp;
                g0n[r] = g_ct[ct];
                g2n[r] = g_ct[ct + 256];
            }

            #pragma unroll
            for (int r = 0; r < RB; r++) {
                float2 p;
                p = lohi(a0[r]);
                float gr = p.x + p.y + base0[r] + g0[r] + yv[r]*wy0;
                float rr = sigf(gr);
                p = lohi(a2[r]);
                float ghh = p.x + p.y + bh2;
                float gxn = gxx2[r] + g2[r] + yv[r]*wy2;
                nsh[r*128 + jp] = tanhc(gxn + rr*ghh);
            }
            __syncthreads();   // nn ready for B

            #pragma unroll
            for (int r = 0; r < RB; r++) {
                yv[r] = yn[r]; g0[r] = g0n[r]; g2[r] = g2n[r];
            }
            __syncthreads();   // hb updated by B
            rd ^= 1;
        }
    } else {
        // ---- group B: gate z (1) + h update ----
        float wy1 = W_ih[(jp+128)*177 + 176];
        float bh1 = b_hh[jp+128];
        float base1[RB];
        #pragma unroll
        for (int r = 0; r < RB; r++)
            base1[r] = bh1 + g_gxx[(size_t)bidx[r]*G3 + jp + 128];
        const ulonglong2* W1 = (const ulonglong2*)(Wsh + (size_t)(jp+128)*132);

        float hcur[RB];
        #pragma unroll
        for (int r = 0; r < RB; r++) {
            hcur[r] = g_h0[bidx[r]*128 + jp];
            hb[r*128 + jp] = hcur[r];
        }

        float yv[RB], mv[RB], g1[RB];
        #pragma unroll
        for (int r = 0; r < RB; r++) {
            int base = bidx[r]*NS;
            int av = a[base], tv = t[base];
            yv[r] = y[base]; mv[r] = mask[base];
            g1[r] = g_ct[(av*4 + tv)*G3 + jp + 128];
        }
        __syncthreads();   // matches A's init barrier

        int rd = 0;
        for (int s = 0; s < NS; s++) {
            int avn[RB], tvn[RB]; float yn[RB], mn[RB];
            int sn = (s+1 < NS) ? s+1 : s;
            #pragma unroll
            for (int r = 0; r < RB; r++) {
                int bn = bidx[r]*NS + sn;
                avn[r] = a[bn]; tvn[r] = t[bn];
                yn[r] = y[bn];  mn[r] = mask[bn];
            }

            u64 a1[RB];
            #pragma unroll
            for (int r = 0; r < RB; r++) a1[r] = 0ull;
            const ulonglong2* hp = (const ulonglong2*)(hb + rd*(RB*128));
            #pragma unroll 4
            for (int k4 = 0; k4 < 32; k4++) {
                ulonglong2 w1 = W1[k4];
                #pragma unroll
                for (int r = 0; r < RB; r++) {
                    ulonglong2 hv = hp[r*32 + k4];
                    fma2(a1[r], w1.x, hv.x); fma2(a1[r], w1.y, hv.y);
                }
            }

            float g1n[RB];
            #pragma unroll
            for (int r = 0; r < RB; r++)
                g1n[r] = g_ct[(avn[r]*4 + tvn[r])*G3 + jp + 128];

            float zz[RB];
            #pragma unroll
            for (int r = 0; r < RB; r++) {
                float2 p = lohi(a1[r]);
                float gz = p.x + p.y + base1[r] + g1[r] + yv[r]*wy1;
                zz[r] = sigf(gz);
            }
            __syncthreads();   // nn ready

            float* hw = hb + (rd^1)*(RB*128);
            #pragma unroll
            for (int r = 0; r < RB; r++) {
                float hold = hcur[r];
                float nn = nsh[r*128 + jp];
                float hn = (1.f - zz[r])*nn + zz[r]*hold;
                float hnew = mv[r]*hn + (1.f - mv[r])*hold;
                hseq[(size_t)bidx[r]*NS*128 + (size_t)s*128 + jp] = hold;
                hw[r*128 + jp] = hnew;
                hcur[r] = hnew;
            }
            #pragma unroll
            for (int r = 0; r < RB; r++) {
                yv[r] = yn[r]; mv[r] = mn[r]; g1[r] = g1n[r];
            }
            __syncthreads();   // hb ready
            rd ^= 1;
        }
    }
}

// ---------------- Phase C ----------------
#define HPW 264
#define NTILE (NM/64)
__global__ void __launch_bounds__(512,1) k_headsp(
    const int* __restrict__ a, const int* __restrict__ t,
    const float* __restrict__ tW1, const float* __restrict__ tb1,
    const float* __restrict__ tW2, const float* __restrict__ tb2,
    const float* __restrict__ yW1,
    const float* __restrict__ yW2, const float* __restrict__ yb2,
    float* __restrict__ dout)
{
    extern __shared__ float sm[];
    float* Ws   = sm;                  // [k 128][n 264]
    float* hs   = Ws + 128*HPW;        // 2 x [64][128]
    float* tb1s = hs + 2*64*128;
    float* tW2s = tb1s + 128;
    float* yW2s = tW2s + 512;
    float* cst  = yW2s + 128;

    int tid = threadIdx.x;
    for (int e = tid; e < 256*128; e += 512) {
        int n = e >> 7, k = e & 127;
        Ws[k*HPW + n] = (n < 128) ? tW1[n*128 + k] : yW1[(size_t)(n-128)*304 + k];
    }
    if (tid < 128) { tb1s[tid] = tb1[tid]; yW2s[tid] = yW2[tid]; }
    tW2s[tid] = tW2[tid];
    if (tid < 4) cst[tid] = tb2[tid];
    if (tid == 4) cst[4] = yb2[0];

    const float* hseq = dout + (size_t)NM*5;
    unsigned hs_u = (unsigned)__cvta_generic_to_shared(hs);

    int tile = blockIdx.x;
    {
        const float* src = hseq + (size_t)tile*8192;
        #pragma unroll
        for (int c = 0; c < 4; c++) {
            int j = tid + c*512;
            cpa16(hs_u + j*16, src + j*4);
        }
        asm volatile("cp.async.commit_group;" ::: "memory");
    }
    __syncthreads();

    int wid = tid >> 5, lane = tid & 31;
    int yh = (wid >= 8);
    int mB = (wid & 7) * 8;
    int nws = lane*4 + (yh ? 128 : 0);
    const float RS2 = 0.70710678118654752f;

    int buf = 0;
    for (; tile < NTILE; tile += 148) {
        if (tile + 148 < NTILE) {
            const float* src = hseq + (size_t)(tile+148)*8192;
            unsigned dst = hs_u + (buf^1)*32768;
            #pragma unroll
            for (int c = 0; c < 4; c++) {
                int j = tid + c*512;
                cpa16(dst + j*16, src + j*4);
            }
            asm volatile("cp.async.commit_group;" ::: "memory");
            asm volatile("cp.async.wait_group 1;" ::: "memory");
        } else {
            asm volatile("cp.async.wait_group 0;" ::: "memory");
        }
        __syncthreads();

        const float* hbuf = hs + buf*8192;
        u64 acc[8][2];
        #pragma unroll
        for (int i = 0; i < 8; i++) { acc[i][0] = 0ull; acc[i][1] = 0ull; }

        for (int k4 = 0; k4 < 32; k4++) {
            float4 av[8];
            #pragma unroll
            for (int i = 0; i < 8; i++)
                av[i] = *(const float4*)&hbuf[(mB+i)*128 + k4*4];
            #pragma unroll
            for (int kk = 0; kk < 4; kk++) {
                ulonglong2 bv = *(const ulonglong2*)&Ws[(k4*4+kk)*HPW + nws];
                #pragma unroll
                for (int i = 0; i < 8; i++) {
                    float as = (kk==0)?av[i].x:(kk==1)?av[i].y:(kk==2)?av[i].z:av[i].w;
                    u64 ad = dup2(as);
                    fma2(acc[i][0], ad, bv.x);
                    fma2(acc[i][1], ad, bv.y);
                }
            }
        }
        __syncthreads();

        #pragma unroll
        for (int i = 0; i < 8; i++) {
            int mg = tile*64 + mB + i;
            float2 c0 = lohi(acc[i][0]), c1 = lohi(acc[i][1]);
            float v[4] = {c0.x, c0.y, c1.x, c1.y};
            if (!yh) {
                float p0=0.f, p1=0.f, p2=0.f, p3=0.f;
                #pragma unroll
                for (int jj = 0; jj < 4; jj++) {
                    int n = lane*4 + jj;
                    float u = v[jj] + tb1s[n];
                    float g = 0.5f*u*(1.f + erff(u*RS2));
                    p0 = fmaf(g, tW2s[n],       p0);
                    p1 = fmaf(g, tW2s[128 + n], p1);
                    p2 = fmaf(g, tW2s[256 + n], p2);
                    p3 = fmaf(g, tW2s[384 + n], p3);
                }
                #pragma unroll
                for (int o = 16; o; o >>= 1) {
                    p0 += __shfl_xor_sync(0xffffffffu, p0, o);
                    p1 += __shfl_xor_sync(0xffffffffu, p1, o);
                    p2 += __shfl_xor_sync(0xffffffffu, p2, o);
                    p3 += __shfl_xor_sync(0xffffffffu, p3, o);
                }
                if (lane == 0) {
                    float* to = dout + (size_t)NM + (size_t)mg*4;
                    to[0] = p0 + cst[0]; to[1] = p1 + cst[1];
                    to[2] = p2 + cst[2]; to[3] = p3 + cst[3];
                }
            } else {
                int bq = mg >> 9;
                const float* yx = g_yxc + bq*128;
                const float* ay = g_ayt + a[mg]*128;
                const float* ty = g_tyt + t[mg]*128;
                float py = 0.f;
                #pragma unroll
                for (int jj = 0; jj < 4; jj++) {
                    int n = lane*4 + jj;
                    float u = v[jj] + yx[n] + ay[n] + ty[n];
                    float g = 0.5f*u*(1.f + erff(u*RS2));
                    py = fmaf(g, yW2s[n], py);
                }
                #pragma unroll
                for (int o = 16; o; o >>= 1)
                    py += __shfl_xor_sync(0xffffffffu, py, o);
                if (lane == 0) dout[mg] = py + cst[4];
            }
        }
        buf ^= 1;
    }
}

// ---------------- launch ----------------
extern "C" void kernel_launch(void* const* d_in, const int* in_sizes, int n_in,
                              void* d_out, int out_size)
{
    const float* x     = (const float*)d_in[0];
    const int*   a     = (const int*)  d_in[1];
    const int*   t     = (const int*)  d_in[2];
    const float* y     = (const float*)d_in[3];
    const float* mask  = (const float*)d_in[4];
    const float* xW    = (const float*)d_in[5];
    const float* xb    = (const float*)d_in[6];
    const float* a_emb = (const float*)d_in[7];
    const float* t_emb = (const float*)d_in[8];
    const float* W_ih  = (const float*)d_in[9];
    const float* b_ih  = (const float*)d_in[10];
    const float* W_hh  = (const float*)d_in[11];
    const float* b_hh  = (const float*)d_in[12];
    const float* h0W   = (const float*)d_in[13];
    const float* h0b   = (const float*)d_in[14];
    const float* tW1   = (const float*)d_in[15];
    const float* tb1   = (const float*)d_in[16];
    const float* tW2   = (const float*)d_in[17];
    const float* tb2   = (const float*)d_in[18];
    const float* yW1   = (const float*)d_in[19];
    const float* yb1   = (const float*)d_in[20];
    const float* yW2   = (const float*)d_in[21];
    const float* yb2   = (const float*)d_in[22];
    float* out = (float*)d_out;

    float* p_xenc;
    cudaGetSymbolAddress((void**)&p_xenc, g_xenc);

    k_tab<<<208, 384>>>(a_emb, t_emb, W_ih, yW1);
    k_gemm<<<dim3(2,16), 256>>>(x, xW, 128, xb, p_xenc, 0);
    k_gemm3<<<dim3(6,16,4), 256>>>(W_ih, b_ih, yW1, yb1, h0W, h0b);

    size_t smB = (size_t)(384*132 + 2*RB*128 + RB*128) * sizeof(float);
    cudaFuncSetAttribute(k_rec, cudaFuncAttributeMaxDynamicSharedMemorySize, (int)smB);
    k_rec<<<(NB + RB - 1)/RB, 256, smB>>>(a, t, y, mask, W_hh, b_hh, W_ih, out);

    size_t smC = (size_t)(128*HPW + 2*64*128 + 128 + 512 + 128 + 8) * sizeof(float);
    cudaFuncSetAttribute(k_headsp, cudaFuncAttributeMaxDynamicSharedMemorySize, (int)smC);
    k_headsp<<<148, 512, smC>>>(a, t, tW1, tb1, tW2, tb2, yW1, yW2, yb2, out);
}

// round 11
// speedup vs baseline: 1.1949x; 1.1949x over previous
#include <cuda_runtime.h>
#include <math.h>

#define NB 1024
#define NS 512
#define NM (NB*NS)
#define G3 384
#define RB 7

typedef unsigned long long u64;

__device__ float g_xenc[NB*128];
__device__ float g_h0[NB*128];
__device__ float g_gxx[NB*G3];
__device__ float g_yxc[NB*128];
__device__ float g_agt[100*G3];
__device__ float g_tgt[4*G3];
__device__ float g_ayt[100*128];
__device__ float g_tyt[4*128];
__device__ float g_ct[400*G3];

__device__ __forceinline__ void fma2(u64& d, u64 a, u64 b) {
    asm("fma.rn.f32x2 %0, %1, %2, %0;" : "+l"(d) : "l"(a), "l"(b));
}
__device__ __forceinline__ u64 dup2(float v) {
    u64 r; asm("mov.b64 %0, {%1, %1};" : "=l"(r) : "f"(v)); return r;
}
__device__ __forceinline__ float2 lohi(u64 v) {
    float2 r; asm("mov.b64 {%0, %1}, %2;" : "=f"(r.x), "=f"(r.y) : "l"(v)); return r;
}
__device__ __forceinline__ float rcpa(float x) {
    float r; asm("rcp.approx.f32 %0, %1;" : "=f"(r) : "f"(x)); return r;
}
__device__ __forceinline__ float sigf(float x) {
    return rcpa(1.f + __expf(-x));
}
__device__ __forceinline__ float tanhc(float v) {
    v = fminf(fmaxf(v, -20.f), 20.f);
    float e = __expf(-2.f*v);
    return (1.f - e) * rcpa(1.f + e);
}
__device__ __forceinline__ void cpa16(unsigned dst, const void* src) {
    asm volatile("cp.async.cg.shared.global [%0], [%1], 16;" :: "r"(dst), "l"(src));
}

// ---------------- Phase A ----------------
#define GBM 64
#define GBN 64
#define GBK 32
__device__ __forceinline__ void gemm_body(
    const float* __restrict__ in,
    const float* __restrict__ W, int ldw, int wofs,
    const float* __restrict__ bias,
    float* __restrict__ out, int ldout, int act,
    int m0, int n0, int tid)
{
    __shared__ float As[GBK][GBM+4];
    __shared__ float Bs[GBK][GBN+4];
    int tx = tid & 15, ty = tid >> 4;
    float acc[4][4] = {};
    for (int k0 = 0; k0 < 128; k0 += GBK) {
        for (int l = tid; l < GBM*GBK/4; l += 256) {
            int row = l >> 3, c4 = l & 7;
            float4 v = *(const float4*)&in[(size_t)(m0+row)*128 + k0 + c4*4];
            As[c4*4+0][row] = v.x; As[c4*4+1][row] = v.y;
            As[c4*4+2][row] = v.z; As[c4*4+3][row] = v.w;
        }
        for (int l = tid; l < GBN*GBK; l += 256) {
            int row = l >> 5, kk = l & 31;
            Bs[kk][row] = W[(size_t)(n0+row)*ldw + wofs + k0 + kk];
        }
        __syncthreads();
        #pragma unroll
        for (int k = 0; k < GBK; k++) {
            float4 a4 = *(const float4*)&As[k][ty*4];
            float4 b4 = *(const float4*)&Bs[k][tx*4];
            float af[4] = {a4.x,a4.y,a4.z,a4.w};
            float bf[4] = {b4.x,b4.y,b4.z,b4.w};
            #pragma unroll
            for (int i = 0; i < 4; i++)
                #pragma unroll
                for (int j = 0; j < 4; j++)
                    acc[i][j] = fmaf(af[i], bf[j], acc[i][j]);
        }
        __syncthreads();
    }
    #pragma unroll
    for (int i = 0; i < 4; i++) {
        int m = m0 + ty*4 + i;
        #pragma unroll
        for (int j = 0; j < 4; j++) {
            int n = n0 + tx*4 + j;
            float v = acc[i][j] + bias[n];
            if (act) v = tanhf(v);
            out[(size_t)m*ldout + n] = v;
        }
    }
}

__global__ void __launch_bounds__(256) k_gemm(
    const float* __restrict__ in,
    const float* __restrict__ W, int ldw,
    const float* __restrict__ bias,
    float* __restrict__ out, int act)
{
    gemm_body(in, W, ldw, 0, bias, out, 128, act,
              blockIdx.y*GBM, blockIdx.x*GBN, threadIdx.x);
}

// z=0..2: gemms off g_xenc; z=3: build combined gate table g_ct
__global__ void __launch_bounds__(256) k_gemm3(
    const float* __restrict__ W_ih, const float* __restrict__ b_ih,
    const float* __restrict__ yW1, const float* __restrict__ yb1,
    const float* __restrict__ h0W, const float* __restrict__ h0b)
{
    int z = blockIdx.z;
    if (z == 3) {
        int lin = blockIdx.y*6 + blockIdx.x;   // 0..95
        #pragma unroll
        for (int q = 0; q < 5; q++) {
            int p = lin*5 + q;
            if (p < 400) {
                int av = p >> 2, tv = p & 3;
                for (int j = threadIdx.x; j < G3; j += 256)
                    g_ct[p*G3 + j] = g_agt[av*G3 + j] + g_tgt[tv*G3 + j];
            }
        }
        return;
    }
    const float *W, *bias; float* out; int ldw, wofs, Nout, ldout, act;
    if (z == 0)      { W=W_ih; bias=b_ih; out=g_gxx; ldw=177; wofs=0;   Nout=384; ldout=384; act=0; }
    else if (z == 1) { W=yW1;  bias=yb1;  out=g_yxc; ldw=304; wofs=128; Nout=128; ldout=128; act=0; }
    else             { W=h0W;  bias=h0b;  out=g_h0;  ldw=128; wofs=0;   Nout=128; ldout=128; act=1; }
    if ((int)blockIdx.x*GBN >= Nout) return;
    gemm_body(g_xenc, W, ldw, wofs, bias, out, ldout, act,
              blockIdx.y*GBM, blockIdx.x*GBN, threadIdx.x);
}

__global__ void __launch_bounds__(384) k_tab(
    const float* __restrict__ a_emb, const float* __restrict__ t_emb,
    const float* __restrict__ W_ih, const float* __restrict__ yW1)
{
    __shared__ float e[32];
    int bid = blockIdx.x, j = threadIdx.x;
    if (bid < 100) {
        int m = bid;
        if (j < 32) e[j] = a_emb[m*32+j];
        __syncthreads();
        float s = 0.f;
        #pragma unroll
        for (int k = 0; k < 32; k++) s += e[k]*W_ih[(size_t)j*177 + 128 + k];
        g_agt[m*G3 + j] = s;
    } else if (bid < 104) {
        int m = bid - 100;
        if (j < 16) e[j] = t_emb[m*16+j];
        __syncthreads();
        float s = 0.f;
        #pragma unroll
        for (int k = 0; k < 16; k++) s += e[k]*W_ih[(size_t)j*177 + 160 + k];
        g_tgt[m*G3 + j] = s;
    } else if (bid < 204) {
        int m = bid - 104;
        if (j < 32) e[j] = a_emb[m*32+j];
        __syncthreads();
        if (j < 128) {
            float s = 0.f;
            #pragma unroll
            for (int k = 0; k < 32; k++) s += e[k]*yW1[(size_t)j*304 + 256 + k];
            g_ayt[m*128 + j] = s;
        }
    } else {
        int m = bid - 204;
        if (j < 16) e[j] = t_emb[m*16+j];
        __syncthreads();
        if (j < 128) {
            float s = 0.f;
            #pragma unroll
            for (int k = 0; k < 16; k++) s += e[k]*yW1[(size_t)j*304 + 288 + k];
            g_tyt[m*128 + j] = s;
        }
    }
}

// ---------------- Phase B: round-9 dataflow + smem-staged step scalars ----------------
// 128 threads, thread jp owns 3 gate rows x RB batch rows.
// a/t/y/mask staged in smem in 32-step chunks (double-buffered cp.async).
__global__ void __launch_bounds__(128,1) k_rec(
    const int* __restrict__ a, const int* __restrict__ t,
    const float* __restrict__ y, const float* __restrict__ mask,
    const float* __restrict__ W_hh, const float* __restrict__ b_hh,
    const float* __restrict__ W_ih,
    float* __restrict__ dout)
{
    extern __shared__ float sm[];
    float* Wsh = sm;                         // 384*132
    float* hb  = Wsh + 384*132;              // 2 * RB*128
    int*   sa  = (int*)(hb + 2*RB*128);      // 2 * RB*32
    int*   stg = sa + 2*RB*32;               // 2 * RB*32
    float* sy  = (float*)(stg + 2*RB*32);    // 2 * RB*32
    float* sms = sy + 2*RB*32;               // 2 * RB*32

    int jp = threadIdx.x;
    int b0 = blockIdx.x * RB;

    for (int idx = jp; idx < 384*128; idx += 128)
        Wsh[(idx>>7)*132 + (idx&127)] = W_hh[idx];

    int bidx[RB];
    #pragma unroll
    for (int r = 0; r < RB; r++) {
        int b = b0 + r; if (b > NB-1) b = NB-1;
        bidx[r] = b;
    }

    unsigned sa_u  = (unsigned)__cvta_generic_to_shared(sa);
    unsigned st_u  = (unsigned)__cvta_generic_to_shared(stg);
    unsigned sy_u  = (unsigned)__cvta_generic_to_shared(sy);
    unsigned sms_u = (unsigned)__cvta_generic_to_shared(sms);

    // stage chunk 0 into buf 0 (RB*8 = 56 16B-units per array)
    if (jp < RB*8) {
        int r = jp >> 3, q = jp & 7;
        int go = bidx[r]*NS + q*4;           // chunk 0: s0 = 0
        int so = r*128 + q*16;
        cpa16(sa_u  + so, a    + go);
        cpa16(st_u  + so, t    + go);
        cpa16(sy_u  + so, y    + go);
        cpa16(sms_u + so, mask + go);
    }
    asm volatile("cp.async.commit_group;" ::: "memory");

    // r,z gates: fold b_hh + gxx; n gate: b_hh stays with dot, gxx with x-side
    float wy[3], basev[2][RB], gxx2[RB], bh2;
    #pragma unroll
    for (int g = 0; g < 2; g++) {
        int j = jp + 128*g;
        float bhg = b_hh[j];
        wy[g] = W_ih[j*177 + 176];
        #pragma unroll
        for (int r = 0; r < RB; r++)
            basev[g][r] = bhg + g_gxx[(size_t)bidx[r]*G3 + j];
    }
    {
        int j = jp + 256;
        bh2 = b_hh[j];
        wy[2] = W_ih[j*177 + 176];
        #pragma unroll
        for (int r = 0; r < RB; r++)
            gxx2[r] = g_gxx[(size_t)bidx[r]*G3 + j];
    }

    float hcur[RB];
    #pragma unroll
    for (int r = 0; r < RB; r++) {
        hcur[r] = g_h0[bidx[r]*128 + jp];
        hb[r*128 + jp] = hcur[r];
    }
    asm volatile("cp.async.wait_group 0;" ::: "memory");
    __syncthreads();

    const ulonglong2* W0 = (const ulonglong2*)(Wsh + (size_t)jp*132);
    const ulonglong2* W1 = (const ulonglong2*)(Wsh + (size_t)(jp+128)*132);
    const ulonglong2* W2 = (const ulonglong2*)(Wsh + (size_t)(jp+256)*132);
    float* hseq = dout + (size_t)NM*5;

    int rd = 0, buf = 0;
    for (int s = 0; s < NS; s++) {
        int sidx = s & 31;
        // prefetch next 32-step chunk at chunk start
        if (sidx == 0 && s + 32 < NS) {
            if (jp < RB*8) {
                int r = jp >> 3, q = jp & 7;
                int go = bidx[r]*NS + (s + 32) + q*4;
                int so = ((buf^1)*RB + r)*128 + q*16;
                cpa16(sa_u  + so, a    + go);
                cpa16(st_u  + so, t    + go);
                cpa16(sy_u  + so, y    + go);
                cpa16(sms_u + so, mask + go);
            }
            asm volatile("cp.async.commit_group;" ::: "memory");
        }

        // read step scalars from smem (broadcast LDS), issue gathers
        float yv[RB], mv[RB], gv0[RB], gv1[RB], gv2[RB];
        #pragma unroll
        for (int r = 0; r < RB; r++) {
            int off = (buf*RB + r)*32 + sidx;
            int av = sa[off], tv = stg[off];
            yv[r] = sy[off]; mv[r] = sms[off];
            int ct = (av*4 + tv)*G3 + jp;
            gv0[r] = g_ct[ct];
            gv1[r] = g_ct[ct + 128];
            gv2[r] = g_ct[ct + 256];
        }

        u64 acc[3][RB];
        #pragma unroll
        for (int g = 0; g < 3; g++)
            #pragma unroll
            for (int r = 0; r < RB; r++) acc[g][r] = 0ull;

        const ulonglong2* hp = (const ulonglong2*)(hb + rd*(RB*128));
        #pragma unroll 8
        for (int k4 = 0; k4 < 32; k4++) {
            ulonglong2 w0 = W0[k4], w1 = W1[k4], w2 = W2[k4];
            #pragma unroll
            for (int r = 0; r < RB; r++) {
                ulonglong2 hv = hp[r*32 + k4];
                fma2(acc[0][r], w0.x, hv.x); fma2(acc[0][r], w0.y, hv.y);
                fma2(acc[1][r], w1.x, hv.x); fma2(acc[1][r], w1.y, hv.y);
                fma2(acc[2][r], w2.x, hv.x); fma2(acc[2][r], w2.y, hv.y);
            }
        }

        float* hw = hb + (rd^1)*(RB*128);
        #pragma unroll
        for (int r = 0; r < RB; r++) {
            float2 p;
            p = lohi(acc[0][r]);
            float gr = p.x + p.y + basev[0][r] + gv0[r] + yv[r]*wy[0];
            p = lohi(acc[1][r]);
            float gz = p.x + p.y + basev[1][r] + gv1[r] + yv[r]*wy[1];
            p = lohi(acc[2][r]);
            float ghh = p.x + p.y + bh2;                    // h-side of n gate
            float gxn = gxx2[r] + gv2[r] + yv[r]*wy[2];     // x-side of n gate
            float rr = sigf(gr), zz = sigf(gz);
            float nn = tanhc(gxn + rr*ghh);
            float hn = (1.f - zz)*nn + zz*hcur[r];
            float hnew = mv[r]*hn + (1.f - mv[r])*hcur[r];
            hseq[(size_t)bidx[r]*NS*128 + (size_t)s*128 + jp] = hcur[r];
            hw[r*128 + jp] = hnew;
            hcur[r] = hnew;
        }
        if (sidx == 31) {
            asm volatile("cp.async.wait_group 0;" ::: "memory");
        }
        __syncthreads();
        rd ^= 1;
        if (sidx == 31) buf ^= 1;
    }
}

// ---------------- Phase C ----------------
#define HPW 264
#define NTILE (NM/64)
__global__ void __launch_bounds__(512,1) k_headsp(
    const int* __restrict__ a, const int* __restrict__ t,
    const float* __restrict__ tW1, const float* __restrict__ tb1,
    const float* __restrict__ tW2, const float* __restrict__ tb2,
    const float* __restrict__ yW1,
    const float* __restrict__ yW2, const float* __restrict__ yb2,
    float* __restrict__ dout)
{
    extern __shared__ float sm[];
    float* Ws   = sm;                  // [k 128][n 264]
    float* hs   = Ws + 128*HPW;        // 2 x [64][128]
    float* tb1s = hs + 2*64*128;
    float* tW2s = tb1s + 128;
    float* yW2s = tW2s + 512;
    float* cst  = yW2s + 128;

    int tid = threadIdx.x;
    for (int e = tid; e < 256*128; e += 512) {
        int n = e >> 7, k = e & 127;
        Ws[k*HPW + n] = (n < 128) ? tW1[n*128 + k] : yW1[(size_t)(n-128)*304 + k];
    }
    if (tid < 128) { tb1s[tid] = tb1[tid]; yW2s[tid] = yW2[tid]; }
    tW2s[tid] = tW2[tid];
    if (tid < 4) cst[tid] = tb2[tid];
    if (tid == 4) cst[4] = yb2[0];

    const float* hseq = dout + (size_t)NM*5;
    unsigned hs_u = (unsigned)__cvta_generic_to_shared(hs);

    int tile = blockIdx.x;
    {
        const float* src = hseq + (size_t)tile*8192;
        #pragma unroll
        for (int c = 0; c < 4; c++) {
            int j = tid + c*512;
            cpa16(hs_u + j*16, src + j*4);
        }
        asm volatile("cp.async.commit_group;" ::: "memory");
    }
    __syncthreads();

    int wid = tid >> 5, lane = tid & 31;
    int yh = (wid >= 8);
    int mB = (wid & 7) * 8;
    int nws = lane*4 + (yh ? 128 : 0);
    const float RS2 = 0.70710678118654752f;

    int buf = 0;
    for (; tile < NTILE; tile += 148) {
        if (tile + 148 < NTILE) {
            const float* src = hseq + (size_t)(tile+148)*8192;
            unsigned dst = hs_u + (buf^1)*32768;
            #pragma unroll
            for (int c = 0; c < 4; c++) {
                int j = tid + c*512;
                cpa16(dst + j*16, src + j*4);
            }
            asm volatile("cp.async.commit_group;" ::: "memory");
            asm volatile("cp.async.wait_group 1;" ::: "memory");
        } else {
            asm volatile("cp.async.wait_group 0;" ::: "memory");
        }
        __syncthreads();

        const float* hbuf = hs + buf*8192;
        u64 acc[8][2];
        #pragma unroll
        for (int i = 0; i < 8; i++) { acc[i][0] = 0ull; acc[i][1] = 0ull; }

        for (int k4 = 0; k4 < 32; k4++) {
            float4 av[8];
            #pragma unroll
            for (int i = 0; i < 8; i++)
                av[i] = *(const float4*)&hbuf[(mB+i)*128 + k4*4];
            #pragma unroll
            for (int kk = 0; kk < 4; kk++) {
                ulonglong2 bv = *(const ulonglong2*)&Ws[(k4*4+kk)*HPW + nws];
                #pragma unroll
                for (int i = 0; i < 8; i++) {
                    float as = (kk==0)?av[i].x:(kk==1)?av[i].y:(kk==2)?av[i].z:av[i].w;
                    u64 ad = dup2(as);
                    fma2(acc[i][0], ad, bv.x);
                    fma2(acc[i][1], ad, bv.y);
                }
            }
        }
        __syncthreads();

        #pragma unroll
        for (int i = 0; i < 8; i++) {
            int mg = tile*64 + mB + i;
            float2 c0 = lohi(acc[i][0]), c1 = lohi(acc[i][1]);
            float v[4] = {c0.x, c0.y, c1.x, c1.y};
            if (!yh) {
                float p0=0.f, p1=0.f, p2=0.f, p3=0.f;
                #pragma unroll
                for (int jj = 0; jj < 4; jj++) {
                    int n = lane*4 + jj;
                    float u = v[jj] + tb1s[n];
                    float g = 0.5f*u*(1.f + erff(u*RS2));
                    p0 = fmaf(g, tW2s[n],       p0);
                    p1 = fmaf(g, tW2s[128 + n], p1);
                    p2 = fmaf(g, tW2s[256 + n], p2);
                    p3 = fmaf(g, tW2s[384 + n], p3);
                }
                #pragma unroll
                for (int o = 16; o; o >>= 1) {
                    p0 += __shfl_xor_sync(0xffffffffu, p0, o);
                    p1 += __shfl_xor_sync(0xffffffffu, p1, o);
                    p2 += __shfl_xor_sync(0xffffffffu, p2, o);
                    p3 += __shfl_xor_sync(0xffffffffu, p3, o);
                }
                if (lane == 0) {
                    float* to = dout + (size_t)NM + (size_t)mg*4;
                    to[0] = p0 + cst[0]; to[1] = p1 + cst[1];
                    to[2] = p2 + cst[2]; to[3] = p3 + cst[3];
                }
            } else {
                int bq = mg >> 9;
                const float* yx = g_yxc + bq*128;
                const float* ay = g_ayt + a[mg]*128;
                const float* ty = g_tyt + t[mg]*128;
                float py = 0.f;
                #pragma unroll
                for (int jj = 0; jj < 4; jj++) {
                    int n = lane*4 + jj;
                    float u = v[jj] + yx[n] + ay[n] + ty[n];
                    float g = 0.5f*u*(1.f + erff(u*RS2));
                    py = fmaf(g, yW2s[n], py);
                }
                #pragma unroll
                for (int o = 16; o; o >>= 1)
                    py += __shfl_xor_sync(0xffffffffu, py, o);
                if (lane == 0) dout[mg] = py + cst[4];
            }
        }
        buf ^= 1;
    }
}

// ---------------- launch ----------------
extern "C" void kernel_launch(void* const* d_in, const int* in_sizes, int n_in,
                              void* d_out, int out_size)
{
    const float* x     = (const float*)d_in[0];
    const int*   a     = (const int*)  d_in[1];
    const int*   t     = (const int*)  d_in[2];
    const float* y     = (const float*)d_in[3];
    const float* mask  = (const float*)d_in[4];
    const float* xW    = (const float*)d_in[5];
    const float* xb    = (const float*)d_in[6];
    const float* a_emb = (const float*)d_in[7];
    const float* t_emb = (const float*)d_in[8];
    const float* W_ih  = (const float*)d_in[9];
    const float* b_ih  = (const float*)d_in[10];
    const float* W_hh  = (const float*)d_in[11];
    const float* b_hh  = (const float*)d_in[12];
    const float* h0W   = (const float*)d_in[13];
    const float* h0b   = (const float*)d_in[14];
    const float* tW1   = (const float*)d_in[15];
    const float* tb1   = (const float*)d_in[16];
    const float* tW2   = (const float*)d_in[17];
    const float* tb2   = (const float*)d_in[18];
    const float* yW1   = (const float*)d_in[19];
    const float* yb1   = (const float*)d_in[20];
    const float* yW2   = (const float*)d_in[21];
    const float* yb2   = (const float*)d_in[22];
    float* out = (float*)d_out;

    float* p_xenc;
    cudaGetSymbolAddress((void**)&p_xenc, g_xenc);

    k_tab<<<208, 384>>>(a_emb, t_emb, W_ih, yW1);
    k_gemm<<<dim3(2,16), 256>>>(x, xW, 128, xb, p_xenc, 0);
    k_gemm3<<<dim3(6,16,4), 256>>>(W_ih, b_ih, yW1, yb1, h0W, h0b);

    size_t smB = (size_t)(384*132 + 2*RB*128 + 4*2*RB*32) * sizeof(float);
    cudaFuncSetAttribute(k_rec, cudaFuncAttributeMaxDynamicSharedMemorySize, (int)smB);
    k_rec<<<(NB + RB - 1)/RB, 128, smB>>>(a, t, y, mask, W_hh, b_hh, W_ih, out);

    size_t smC = (size_t)(128*HPW + 2*64*128 + 128 + 512 + 128 + 8) * sizeof(float);
    cudaFuncSetAttribute(k_headsp, cudaFuncAttributeMaxDynamicSharedMemorySize, (int)smC);
    k_headsp<<<148, 512, smC>>>(a, t, tW1, tb1, tW2, tb2, yW1, yW2, yb2, out);
}

// round 12
// speedup vs baseline: 1.2106x; 1.0132x over previous
#include <cuda_runtime.h>
#include <math.h>

#define NB 1024
#define NS 512
#define NM (NB*NS)
#define G3 384
#define RB 7

typedef unsigned long long u64;

__device__ float g_xenc[NB*128];
__device__ float g_h0[NB*128];
__device__ float g_gxx[NB*G3];
__device__ float g_yxc[NB*128];
__device__ float g_agt[100*G3];
__device__ float g_tgt[4*G3];
__device__ float g_ayt[100*128];
__device__ float g_tyt[4*128];
__device__ float g_ct[400*G3];

__device__ __forceinline__ void fma2(u64& d, u64 a, u64 b) {
    asm("fma.rn.f32x2 %0, %1, %2, %0;" : "+l"(d) : "l"(a), "l"(b));
}
__device__ __forceinline__ u64 dup2(float v) {
    u64 r; asm("mov.b64 %0, {%1, %1};" : "=l"(r) : "f"(v)); return r;
}
__device__ __forceinline__ float2 lohi(u64 v) {
    float2 r; asm("mov.b64 {%0, %1}, %2;" : "=f"(r.x), "=f"(r.y) : "l"(v)); return r;
}
__device__ __forceinline__ float rcpa(float x) {
    float r; asm("rcp.approx.f32 %0, %1;" : "=f"(r) : "f"(x)); return r;
}
__device__ __forceinline__ float sigf(float x) {
    return rcpa(1.f + __expf(-x));
}
__device__ __forceinline__ float tanhc(float v) {
    v = fminf(fmaxf(v, -20.f), 20.f);
    float e = __expf(-2.f*v);
    return (1.f - e) * rcpa(1.f + e);
}
__device__ __forceinline__ void cpa16(unsigned dst, const void* src) {
    asm volatile("cp.async.cg.shared.global [%0], [%1], 16;" :: "r"(dst), "l"(src));
}

// ---------------- Phase A ----------------
#define GBM 64
#define GBN 64
#define GBK 32
__device__ __forceinline__ void gemm_body(
    const float* __restrict__ in,
    const float* __restrict__ W, int ldw, int wofs,
    const float* __restrict__ bias,
    float* __restrict__ out, int ldout, int act,
    int m0, int n0, int tid)
{
    __shared__ float As[GBK][GBM+4];
    __shared__ float Bs[GBK][GBN+4];
    int tx = tid & 15, ty = tid >> 4;
    float acc[4][4] = {};
    for (int k0 = 0; k0 < 128; k0 += GBK) {
        for (int l = tid; l < GBM*GBK/4; l += 256) {
            int row = l >> 3, c4 = l & 7;
            float4 v = *(const float4*)&in[(size_t)(m0+row)*128 + k0 + c4*4];
            As[c4*4+0][row] = v.x; As[c4*4+1][row] = v.y;
            As[c4*4+2][row] = v.z; As[c4*4+3][row] = v.w;
        }
        for (int l = tid; l < GBN*GBK; l += 256) {
            int row = l >> 5, kk = l & 31;
            Bs[kk][row] = W[(size_t)(n0+row)*ldw + wofs + k0 + kk];
        }
        __syncthreads();
        #pragma unroll
        for (int k = 0; k < GBK; k++) {
            float4 a4 = *(const float4*)&As[k][ty*4];
            float4 b4 = *(const float4*)&Bs[k][tx*4];
            float af[4] = {a4.x,a4.y,a4.z,a4.w};
            float bf[4] = {b4.x,b4.y,b4.z,b4.w};
            #pragma unroll
            for (int i = 0; i < 4; i++)
                #pragma unroll
                for (int j = 0; j < 4; j++)
                    acc[i][j] = fmaf(af[i], bf[j], acc[i][j]);
        }
        __syncthreads();
    }
    #pragma unroll
    for (int i = 0; i < 4; i++) {
        int m = m0 + ty*4 + i;
        #pragma unroll
        for (int j = 0; j < 4; j++) {
            int n = n0 + tx*4 + j;
            float v = acc[i][j] + bias[n];
            if (act) v = tanhf(v);
            out[(size_t)m*ldout + n] = v;
        }
    }
}

__global__ void __launch_bounds__(256) k_gemm(
    const float* __restrict__ in,
    const float* __restrict__ W, int ldw,
    const float* __restrict__ bias,
    float* __restrict__ out, int act)
{
    gemm_body(in, W, ldw, 0, bias, out, 128, act,
              blockIdx.y*GBM, blockIdx.x*GBN, threadIdx.x);
}

// z=0..2: gemms off g_xenc; z=3: build combined gate table g_ct
__global__ void __launch_bounds__(256) k_gemm3(
    const float* __restrict__ W_ih, const float* __restrict__ b_ih,
    const float* __restrict__ yW1, const float* __restrict__ yb1,
    const float* __restrict__ h0W, const float* __restrict__ h0b)
{
    int z = blockIdx.z;
    if (z == 3) {
        int lin = blockIdx.y*6 + blockIdx.x;   // 0..95
        #pragma unroll
        for (int q = 0; q < 5; q++) {
            int p = lin*5 + q;
            if (p < 400) {
                int av = p >> 2, tv = p & 3;
                for (int j = threadIdx.x; j < G3; j += 256)
                    g_ct[p*G3 + j] = g_agt[av*G3 + j] + g_tgt[tv*G3 + j];
            }
        }
        return;
    }
    const float *W, *bias; float* out; int ldw, wofs, Nout, ldout, act;
    if (z == 0)      { W=W_ih; bias=b_ih; out=g_gxx; ldw=177; wofs=0;   Nout=384; ldout=384; act=0; }
    else if (z == 1) { W=yW1;  bias=yb1;  out=g_yxc; ldw=304; wofs=128; Nout=128; ldout=128; act=0; }
    else             { W=h0W;  bias=h0b;  out=g_h0;  ldw=128; wofs=0;   Nout=128; ldout=128; act=1; }
    if ((int)blockIdx.x*GBN >= Nout) return;
    gemm_body(g_xenc, W, ldw, wofs, bias, out, ldout, act,
              blockIdx.y*GBM, blockIdx.x*GBN, threadIdx.x);
}

__global__ void __launch_bounds__(384) k_tab(
    const float* __restrict__ a_emb, const float* __restrict__ t_emb,
    const float* __restrict__ W_ih, const float* __restrict__ yW1)
{
    __shared__ float e[32];
    int bid = blockIdx.x, j = threadIdx.x;
    if (bid < 100) {
        int m = bid;
        if (j < 32) e[j] = a_emb[m*32+j];
        __syncthreads();
        float s = 0.f;
        #pragma unroll
        for (int k = 0; k < 32; k++) s += e[k]*W_ih[(size_t)j*177 + 128 + k];
        g_agt[m*G3 + j] = s;
    } else if (bid < 104) {
        int m = bid - 100;
        if (j < 16) e[j] = t_emb[m*16+j];
        __syncthreads();
        float s = 0.f;
        #pragma unroll
        for (int k = 0; k < 16; k++) s += e[k]*W_ih[(size_t)j*177 + 160 + k];
        g_tgt[m*G3 + j] = s;
    } else if (bid < 204) {
        int m = bid - 104;
        if (j < 32) e[j] = a_emb[m*32+j];
        __syncthreads();
        if (j < 128) {
            float s = 0.f;
            #pragma unroll
            for (int k = 0; k < 32; k++) s += e[k]*yW1[(size_t)j*304 + 256 + k];
            g_ayt[m*128 + j] = s;
        }
    } else {
        int m = bid - 204;
        if (j < 16) e[j] = t_emb[m*16+j];
        __syncthreads();
        if (j < 128) {
            float s = 0.f;
            #pragma unroll
            for (int k = 0; k < 16; k++) s += e[k]*yW1[(size_t)j*304 + 288 + k];
            g_tyt[m*128 + j] = s;
        }
    }
}

// ---------------- Phase B: round-11 + explicitly software-pipelined dot loop ----------------
__global__ void __launch_bounds__(128,1) k_rec(
    const int* __restrict__ a, const int* __restrict__ t,
    const float* __restrict__ y, const float* __restrict__ mask,
    const float* __restrict__ W_hh, const float* __restrict__ b_hh,
    const float* __restrict__ W_ih,
    float* __restrict__ dout)
{
    extern __shared__ float sm[];
    float* Wsh = sm;                         // 384*132
    float* hb  = Wsh + 384*132;              // 2 * RB*128
    int*   sa  = (int*)(hb + 2*RB*128);      // 2 * RB*32
    int*   stg = sa + 2*RB*32;               // 2 * RB*32
    float* sy  = (float*)(stg + 2*RB*32);    // 2 * RB*32
    float* sms = sy + 2*RB*32;               // 2 * RB*32

    int jp = threadIdx.x;
    int b0 = blockIdx.x * RB;

    for (int idx = jp; idx < 384*128; idx += 128)
        Wsh[(idx>>7)*132 + (idx&127)] = W_hh[idx];

    int bidx[RB];
    #pragma unroll
    for (int r = 0; r < RB; r++) {
        int b = b0 + r; if (b > NB-1) b = NB-1;
        bidx[r] = b;
    }

    unsigned sa_u  = (unsigned)__cvta_generic_to_shared(sa);
    unsigned st_u  = (unsigned)__cvta_generic_to_shared(stg);
    unsigned sy_u  = (unsigned)__cvta_generic_to_shared(sy);
    unsigned sms_u = (unsigned)__cvta_generic_to_shared(sms);

    if (jp < RB*8) {
        int r = jp >> 3, q = jp & 7;
        int go = bidx[r]*NS + q*4;
        int so = r*128 + q*16;
        cpa16(sa_u  + so, a    + go);
        cpa16(st_u  + so, t    + go);
        cpa16(sy_u  + so, y    + go);
        cpa16(sms_u + so, mask + go);
    }
    asm volatile("cp.async.commit_group;" ::: "memory");

    float wy[3], basev[2][RB], gxx2[RB], bh2;
    #pragma unroll
    for (int g = 0; g < 2; g++) {
        int j = jp + 128*g;
        float bhg = b_hh[j];
        wy[g] = W_ih[j*177 + 176];
        #pragma unroll
        for (int r = 0; r < RB; r++)
            basev[g][r] = bhg + g_gxx[(size_t)bidx[r]*G3 + j];
    }
    {
        int j = jp + 256;
        bh2 = b_hh[j];
        wy[2] = W_ih[j*177 + 176];
        #pragma unroll
        for (int r = 0; r < RB; r++)
            gxx2[r] = g_gxx[(size_t)bidx[r]*G3 + j];
    }

    float hcur[RB];
    #pragma unroll
    for (int r = 0; r < RB; r++) {
        hcur[r] = g_h0[bidx[r]*128 + jp];
        hb[r*128 + jp] = hcur[r];
    }
    asm volatile("cp.async.wait_group 0;" ::: "memory");
    __syncthreads();

    const ulonglong2* W0 = (const ulonglong2*)(Wsh + (size_t)jp*132);
    const ulonglong2* W1 = (const ulonglong2*)(Wsh + (size_t)(jp+128)*132);
    const ulonglong2* W2 = (const ulonglong2*)(Wsh + (size_t)(jp+256)*132);
    float* hseq = dout + (size_t)NM*5;

    int rd = 0, buf = 0;
    for (int s = 0; s < NS; s++) {
        int sidx = s & 31;
        if (sidx == 0 && s + 32 < NS) {
            if (jp < RB*8) {
                int r = jp >> 3, q = jp & 7;
                int go = bidx[r]*NS + (s + 32) + q*4;
                int so = ((buf^1)*RB + r)*128 + q*16;
                cpa16(sa_u  + so, a    + go);
                cpa16(st_u  + so, t    + go);
                cpa16(sy_u  + so, y    + go);
                cpa16(sms_u + so, mask + go);
            }
            asm volatile("cp.async.commit_group;" ::: "memory");
        }

        float yv[RB], mv[RB], gv0[RB], gv1[RB], gv2[RB];
        #pragma unroll
        for (int r = 0; r < RB; r++) {
            int off = (buf*RB + r)*32 + sidx;
            int av = sa[off], tv = stg[off];
            yv[r] = sy[off]; mv[r] = sms[off];
            int ct = (av*4 + tv)*G3 + jp;
            gv0[r] = g_ct[ct];
            gv1[r] = g_ct[ct + 128];
            gv2[r] = g_ct[ct + 256];
        }

        u64 acc[3][RB];
        #pragma unroll
        for (int g = 0; g < 3; g++)
            #pragma unroll
            for (int r = 0; r < RB; r++) acc[g][r] = 0ull;

        const ulonglong2* hp = (const ulonglong2*)(hb + rd*(RB*128));

        // software-pipelined dot: loads for k4+1 issue before FMAs of k4
        ulonglong2 cw0 = W0[0], cw1 = W1[0], cw2 = W2[0];
        ulonglong2 ch[RB];
        #pragma unroll
        for (int r = 0; r < RB; r++) ch[r] = hp[r*32];
        #pragma unroll 8
        for (int k4 = 0; k4 < 32; k4++) {
            int kn = (k4 + 1) & 31;
            ulonglong2 nw0 = W0[kn], nw1 = W1[kn], nw2 = W2[kn];
            ulonglong2 nh[RB];
            #pragma unroll
            for (int r = 0; r < RB; r++) nh[r] = hp[r*32 + kn];
            #pragma unroll
            for (int r = 0; r < RB; r++) {
                fma2(acc[0][r], cw0.x, ch[r].x); fma2(acc[0][r], cw0.y, ch[r].y);
                fma2(acc[1][r], cw1.x, ch[r].x); fma2(acc[1][r], cw1.y, ch[r].y);
                fma2(acc[2][r], cw2.x, ch[r].x); fma2(acc[2][r], cw2.y, ch[r].y);
            }
            cw0 = nw0; cw1 = nw1; cw2 = nw2;
            #pragma unroll
            for (int r = 0; r < RB; r++) ch[r] = nh[r];
        }

        float* hw = hb + (rd^1)*(RB*128);
        #pragma unroll
        for (int r = 0; r < RB; r++) {
            float2 p;
            p = lohi(acc[0][r]);
            float gr = p.x + p.y + basev[0][r] + gv0[r] + yv[r]*wy[0];
            p = lohi(acc[1][r]);
            float gz = p.x + p.y + basev[1][r] + gv1[r] + yv[r]*wy[1];
            p = lohi(acc[2][r]);
            float ghh = p.x + p.y + bh2;
            float gxn = gxx2[r] + gv2[r] + yv[r]*wy[2];
            float rr = sigf(gr), zz = sigf(gz);
            float nn = tanhc(gxn + rr*ghh);
            float hn = (1.f - zz)*nn + zz*hcur[r];
            float hnew = mv[r]*hn + (1.f - mv[r])*hcur[r];
            hseq[(size_t)bidx[r]*NS*128 + (size_t)s*128 + jp] = hcur[r];
            hw[r*128 + jp] = hnew;
            hcur[r] = hnew;
        }
        if (sidx == 31) {
            asm volatile("cp.async.wait_group 0;" ::: "memory");
        }
        __syncthreads();
        rd ^= 1;
        if (sidx == 31) buf ^= 1;
    }
}

// ---------------- Phase C ----------------
#define HPW 264
#define NTILE (NM/64)
__global__ void __launch_bounds__(512,1) k_headsp(
    const int* __restrict__ a, const int* __restrict__ t,
    const float* __restrict__ tW1, const float* __restrict__ tb1,
    const float* __restrict__ tW2, const float* __restrict__ tb2,
    const float* __restrict__ yW1,
    const float* __restrict__ yW2, const float* __restrict__ yb2,
    float* __restrict__ dout)
{
    extern __shared__ float sm[];
    float* Ws   = sm;                  // [k 128][n 264]
    float* hs   = Ws + 128*HPW;        // 2 x [64][128]
    float* tb1s = hs + 2*64*128;
    float* tW2s = tb1s + 128;
    float* yW2s = tW2s + 512;
    float* cst  = yW2s + 128;

    int tid = threadIdx.x;
    for (int e = tid; e < 256*128; e += 512) {
        int n = e >> 7, k = e & 127;
        Ws[k*HPW + n] = (n < 128) ? tW1[n*128 + k] : yW1[(size_t)(n-128)*304 + k];
    }
    if (tid < 128) { tb1s[tid] = tb1[tid]; yW2s[tid] = yW2[tid]; }
    tW2s[tid] = tW2[tid];
    if (tid < 4) cst[tid] = tb2[tid];
    if (tid == 4) cst[4] = yb2[0];

    const float* hseq = dout + (size_t)NM*5;
    unsigned hs_u = (unsigned)__cvta_generic_to_shared(hs);

    int tile = blockIdx.x;
    {
        const float* src = hseq + (size_t)tile*8192;
        #pragma unroll
        for (int c = 0; c < 4; c++) {
            int j = tid + c*512;
            cpa16(hs_u + j*16, src + j*4);
        }
        asm volatile("cp.async.commit_group;" ::: "memory");
    }
    __syncthreads();

    int wid = tid >> 5, lane = tid & 31;
    int yh = (wid >= 8);
    int mB = (wid & 7) * 8;
    int nws = lane*4 + (yh ? 128 : 0);
    const float RS2 = 0.70710678118654752f;

    int buf = 0;
    for (; tile < NTILE; tile += 148) {
        if (tile + 148 < NTILE) {
            const float* src = hseq + (size_t)(tile+148)*8192;
            unsigned dst = hs_u + (buf^1)*32768;
            #pragma unroll
            for (int c = 0; c < 4; c++) {
                int j = tid + c*512;
                cpa16(dst + j*16, src + j*4);
            }
            asm volatile("cp.async.commit_group;" ::: "memory");
            asm volatile("cp.async.wait_group 1;" ::: "memory");
        } else {
            asm volatile("cp.async.wait_group 0;" ::: "memory");
        }
        __syncthreads();

        const float* hbuf = hs + buf*8192;
        u64 acc[8][2];
        #pragma unroll
        for (int i = 0; i < 8; i++) { acc[i][0] = 0ull; acc[i][1] = 0ull; }

        for (int k4 = 0; k4 < 32; k4++) {
            float4 av[8];
            #pragma unroll
            for (int i = 0; i < 8; i++)
                av[i] = *(const float4*)&hbuf[(mB+i)*128 + k4*4];
            #pragma unroll
            for (int kk = 0; kk < 4; kk++) {
                ulonglong2 bv = *(const ulonglong2*)&Ws[(k4*4+kk)*HPW + nws];
                #pragma unroll
                for (int i = 0; i < 8; i++) {
                    float as = (kk==0)?av[i].x:(kk==1)?av[i].y:(kk==2)?av[i].z:av[i].w;
                    u64 ad = dup2(as);
                    fma2(acc[i][0], ad, bv.x);
                    fma2(acc[i][1], ad, bv.y);
                }
            }
        }
        __syncthreads();

        #pragma unroll
        for (int i = 0; i < 8; i++) {
            int mg = tile*64 + mB + i;
            float2 c0 = lohi(acc[i][0]), c1 = lohi(acc[i][1]);
            float v[4] = {c0.x, c0.y, c1.x, c1.y};
            if (!yh) {
                float p0=0.f, p1=0.f, p2=0.f, p3=0.f;
                #pragma unroll
                for (int jj = 0; jj < 4; jj++) {
                    int n = lane*4 + jj;
                    float u = v[jj] + tb1s[n];
                    float g = 0.5f*u*(1.f + erff(u*RS2));
                    p0 = fmaf(g, tW2s[n],       p0);
                    p1 = fmaf(g, tW2s[128 + n], p1);
                    p2 = fmaf(g, tW2s[256 + n], p2);
                    p3 = fmaf(g, tW2s[384 + n], p3);
                }
                #pragma unroll
                for (int o = 16; o; o >>= 1) {
                    p0 += __shfl_xor_sync(0xffffffffu, p0, o);
                    p1 += __shfl_xor_sync(0xffffffffu, p1, o);
                    p2 += __shfl_xor_sync(0xffffffffu, p2, o);
                    p3 += __shfl_xor_sync(0xffffffffu, p3, o);
                }
                if (lane == 0) {
                    float* to = dout + (size_t)NM + (size_t)mg*4;
                    to[0] = p0 + cst[0]; to[1] = p1 + cst[1];
                    to[2] = p2 + cst[2]; to[3] = p3 + cst[3];
                }
            } else {
                int bq = mg >> 9;
                const float* yx = g_yxc + bq*128;
                const float* ay = g_ayt + a[mg]*128;
                const float* ty = g_tyt + t[mg]*128;
                float py = 0.f;
                #pragma unroll
                for (int jj = 0; jj < 4; jj++) {
                    int n = lane*4 + jj;
                    float u = v[jj] + yx[n] + ay[n] + ty[n];
                    float g = 0.5f*u*(1.f + erff(u*RS2));
                    py = fmaf(g, yW2s[n], py);
                }
                #pragma unroll
                for (int o = 16; o; o >>= 1)
                    py += __shfl_xor_sync(0xffffffffu, py, o);
                if (lane == 0) dout[mg] = py + cst[4];
            }
        }
        buf ^= 1;
    }
}

// ---------------- launch ----------------
extern "C" void kernel_launch(void* const* d_in, const int* in_sizes, int n_in,
                              void* d_out, int out_size)
{
    const float* x     = (const float*)d_in[0];
    const int*   a     = (const int*)  d_in[1];
    const int*   t     = (const int*)  d_in[2];
    const float* y     = (const float*)d_in[3];
    const float* mask  = (const float*)d_in[4];
    const float* xW    = (const float*)d_in[5];
    const float* xb    = (const float*)d_in[6];
    const float* a_emb = (const float*)d_in[7];
    const float* t_emb = (const float*)d_in[8];
    const float* W_ih  = (const float*)d_in[9];
    const float* b_ih  = (const float*)d_in[10];
    const float* W_hh  = (const float*)d_in[11];
    const float* b_hh  = (const float*)d_in[12];
    const float* h0W   = (const float*)d_in[13];
    const float* h0b   = (const float*)d_in[14];
    const float* tW1   = (const float*)d_in[15];
    const float* tb1   = (const float*)d_in[16];
    const float* tW2   = (const float*)d_in[17];
    const float* tb2   = (const float*)d_in[18];
    const float* yW1   = (const float*)d_in[19];
    const float* yb1   = (const float*)d_in[20];
    const float* yW2   = (const float*)d_in[21];
    const float* yb2   = (const float*)d_in[22];
    float* out = (float*)d_out;

    float* p_xenc;
    cudaGetSymbolAddress((void**)&p_xenc, g_xenc);

    k_tab<<<208, 384>>>(a_emb, t_emb, W_ih, yW1);
    k_gemm<<<dim3(2,16), 256>>>(x, xW, 128, xb, p_xenc, 0);
    k_gemm3<<<dim3(6,16,4), 256>>>(W_ih, b_ih, yW1, yb1, h0W, h0b);

    size_t smB = (size_t)(384*132 + 2*RB*128 + 4*2*RB*32) * sizeof(float);
    cudaFuncSetAttribute(k_rec, cudaFuncAttributeMaxDynamicSharedMemorySize, (int)smB);
    k_rec<<<(NB + RB - 1)/RB, 128, smB>>>(a, t, y, mask, W_hh, b_hh, W_ih, out);

    size_t smC = (size_t)(128*HPW + 2*64*128 + 128 + 512 + 128 + 8) * sizeof(float);
    cudaFuncSetAttribute(k_headsp, cudaFuncAttributeMaxDynamicSharedMemorySize, (int)smC);
    k_headsp<<<148, 512, smC>>>(a, t, tW1, tb1, tW2, tb2, yW1, yW2, yb2, out);
}